// round 16
// baseline (speedup 1.0000x reference)
#include <cuda_runtime.h>
#include <cuda_fp16.h>
#include <math.h>
#include <stdint.h>

// Problem constants: n=2048, b=4, d=1024, E=2, h=512
#define NSEQ   2048
#define NBATCH 4
#define DDIM   1024
#define D3     (3*DDIM)
#define HDIM   512
#define NROWS  (NSEQ*NBATCH)   // 8192
#define SEG    64
#define LSEG   (NSEQ/SEG)      // 32

// GEMM: pure fp16 single-pass.
#define PK     1024
#define BM     128
#define BN     128
#define BKE    64
#define STAGES 3
#define NIT    16
#define ABYTES      16384
#define STAGE_BYTES 32768
#define SMEM_GEMM   (STAGES * STAGE_BYTES)   // 96 KB

#define SWZ(r, c) ((uint32_t)((r)*128 + (((c) ^ ((r)&7))*16)))

// ---------------- scratch (device globals; no cudaMalloc allowed) ----------
__device__ __half g_inp[(size_t)NROWS * DDIM];      // 16 MB  silu(inp), fp16
__device__ __half g_og [(size_t)NROWS * DDIM];      // 16 MB  sigm(og),  fp16
__device__ float  g_lam[(size_t)NROWS * DDIM];      // 32 MB  lambda,    fp32
__device__ float g_segA[2*NBATCH*SEG*HDIM*2];
__device__ float g_segB[2*NBATCH*SEG*HDIM*4];
__device__ float g_carry[2*NBATCH*SEG*HDIM*4];
__device__ float g_outf[(size_t)NROWS * DDIM];
__device__ float g_outr[(size_t)NROWS * DDIM];
__device__ __half g_Ah[(size_t)NROWS * PK];         // 16 MB
__device__ __half g_Bh[(size_t)D3 * PK];            // 6 MB

// ======================= PTX helpers ========================================
__device__ __forceinline__ uint32_t smem_u32(const void* p) {
    uint32_t a;
    asm("{ .reg .u64 t; cvta.to.shared.u64 t, %1; cvt.u32.u64 %0, t; }" : "=r"(a) : "l"(p));
    return a;
}
__device__ __forceinline__ void cpa16(uint32_t dst, const void* src) {
    asm volatile("cp.async.cg.shared.global [%0], [%1], 16;" :: "r"(dst), "l"(src));
}
#define CP_COMMIT() asm volatile("cp.async.commit_group;" ::: "memory")
#define CP_WAIT(n)  asm volatile("cp.async.wait_group %0;" :: "n"(n) : "memory")

__device__ __forceinline__ void ldsm4(uint32_t& r0, uint32_t& r1, uint32_t& r2,
                                      uint32_t& r3, uint32_t addr) {
    asm volatile("ldmatrix.sync.aligned.m8n8.x4.shared.b16 {%0,%1,%2,%3}, [%4];"
                 : "=r"(r0), "=r"(r1), "=r"(r2), "=r"(r3) : "r"(addr));
}
__device__ __forceinline__ void mma16816(float* d, const uint32_t* a, const uint32_t* b) {
    asm volatile("mma.sync.aligned.m16n8k16.row.col.f32.f16.f16.f32 "
        "{%0,%1,%2,%3}, {%4,%5,%6,%7}, {%8,%9}, {%0,%1,%2,%3};"
        : "+f"(d[0]), "+f"(d[1]), "+f"(d[2]), "+f"(d[3])
        : "r"(a[0]), "r"(a[1]), "r"(a[2]), "r"(a[3]), "r"(b[0]), "r"(b[1]));
}

__device__ __forceinline__ float fsig(float x) { return 1.f / (1.f + __expf(-x)); }

// ======================= conversion kernels =================================
__global__ __launch_bounds__(256)
void convA_kernel(const float* __restrict__ X, __half* __restrict__ A)
{
    size_t t = (size_t)blockIdx.x * blockDim.x + threadIdx.x;
    size_t idx = t * 4;
    float4 v = *(const float4*)&X[idx];
    __half2 H01 = __halves2half2(__float2half_rn(v.x), __float2half_rn(v.y));
    __half2 H23 = __halves2half2(__float2half_rn(v.z), __float2half_rn(v.w));
    *reinterpret_cast<__half2*>(A + idx)     = H01;
    *reinterpret_cast<__half2*>(A + idx + 2) = H23;
}

__global__ __launch_bounds__(256)
void convB_kernel(const float* __restrict__ W, __half* __restrict__ Bp, int N)
{
    __shared__ float tile[32][33];
    int n0 = blockIdx.x * 32, k0 = blockIdx.y * 32;
    int tx = threadIdx.x & 31, ty = threadIdx.x >> 5;
    #pragma unroll
    for (int j = 0; j < 32; j += 8)
        tile[ty + j][tx] = W[(size_t)(k0 + ty + j) * N + n0 + tx];
    __syncthreads();
    #pragma unroll
    for (int j = 0; j < 32; j += 8) {
        int n = n0 + ty + j;
        int k = k0 + tx;
        Bp[(size_t)n * PK + k] = __float2half_rn(tile[tx][ty + j]);
    }
}

// ======================= HMMA GEMM (fp16, 1-pass) ===========================
__device__ __forceinline__ void load_stage(uint32_t sA, uint32_t sB,
    const __half* Ab, const __half* Bb, int ist, int tid)
{
    int k0 = ist * BKE;
    #pragma unroll
    for (int q = 0; q < 4; q++) {
        int g = tid + q * 256;
        int r = g >> 3, c = g & 7;
        uint32_t off = SWZ(r, c);
        cpa16(sA + off, Ab + (size_t)r * PK + k0 + c * 8);
        cpa16(sB + off, Bb + (size_t)r * PK + k0 + c * 8);
    }
}

// act=1: gates epilogue writes inp/og fp16, lambda fp32. act=0: fp32 C+bias.
__global__ __launch_bounds__(256, 2)
void gemm_mma(const __half* __restrict__ A, const __half* __restrict__ B,
              const float* __restrict__ bias, float* __restrict__ C, int N,
              const float* __restrict__ lbp, int act,
              __half* __restrict__ inp_out, __half* __restrict__ og_out,
              float* __restrict__ lam_out)
{
    extern __shared__ __align__(1024) char smem[];
    uint32_t sb = smem_u32(smem);

    const int tid  = threadIdx.x;
    const int wid  = tid >> 5;
    const int lane = tid & 31;
    const int m0 = blockIdx.y * BM;
    const int n0 = blockIdx.x * BN;
    const int wm = (wid >> 2) * 64;
    const int wn = (wid & 3) * 32;

    const __half* Ab = A + (size_t)m0 * PK;
    const __half* Bb = B + (size_t)n0 * PK;

    float d[4][4][4];
    #pragma unroll
    for (int i = 0; i < 4; i++)
        #pragma unroll
        for (int j = 0; j < 4; j++)
            #pragma unroll
            for (int q = 0; q < 4; q++) d[i][j][q] = 0.f;

    #pragma unroll
    for (int s = 0; s < STAGES - 1; s++) {
        load_stage(sb + s * STAGE_BYTES, sb + s * STAGE_BYTES + ABYTES, Ab, Bb, s, tid);
        CP_COMMIT();
    }

    const int a_row = wm + (lane & 15);
    const int a_ch  = (lane >> 4);
    const int b_row = wn + ((lane >> 4) * 8) + (lane & 7);
    const int b_ch  = ((lane >> 3) & 1);

    for (int it = 0; it < NIT; it++) {
        CP_WAIT(STAGES - 2);
        __syncthreads();

        if (it + STAGES - 1 < NIT) {
            int s = (it + STAGES - 1) % STAGES;
            load_stage(sb + s * STAGE_BYTES, sb + s * STAGE_BYTES + ABYTES,
                       Ab, Bb, it + STAGES - 1, tid);
        }
        CP_COMMIT();

        uint32_t sA = sb + (it % STAGES) * STAGE_BYTES;
        uint32_t sB = sA + ABYTES;

        #pragma unroll
        for (int kk = 0; kk < 4; kk++) {
            uint32_t a[4][4], b[2][4];
            #pragma unroll
            for (int mt = 0; mt < 4; mt++) {
                uint32_t addr = sA + SWZ(a_row + mt * 16, a_ch + kk * 2);
                ldsm4(a[mt][0], a[mt][1], a[mt][2], a[mt][3], addr);
            }
            #pragma unroll
            for (int nt2 = 0; nt2 < 2; nt2++) {
                uint32_t addr = sB + SWZ(b_row + nt2 * 16, b_ch + kk * 2);
                ldsm4(b[nt2][0], b[nt2][1], b[nt2][2], b[nt2][3], addr);
            }
            #pragma unroll
            for (int mt = 0; mt < 4; mt++)
                #pragma unroll
                for (int nt = 0; nt < 4; nt++)
                    mma16816(d[mt][nt], a[mt], &b[nt >> 1][(nt & 1) * 2]);
        }
    }

    const int grp = lane >> 2;
    const int tig = lane & 3;
    #pragma unroll
    for (int mt = 0; mt < 4; mt++) {
        int row0 = m0 + wm + mt * 16 + grp;
        #pragma unroll
        for (int nt = 0; nt < 4; nt++) {
            int col = n0 + wn + nt * 8 + tig * 2;
            float2 bv = *(const float2*)&bias[col];
            float vx0 = d[mt][nt][0] + bv.x, vy0 = d[mt][nt][1] + bv.y;
            float vx1 = d[mt][nt][2] + bv.x, vy1 = d[mt][nt][3] + bv.y;
            if (act) {
                // each CTA's col range lies entirely in one third (BN|1024)
                if (col < DDIM) {              // silu(inp) -> fp16
                    vx0 *= fsig(vx0); vy0 *= fsig(vy0);
                    vx1 *= fsig(vx1); vy1 *= fsig(vy1);
                    *reinterpret_cast<__half2*>(&inp_out[(size_t)row0 * DDIM + col]) =
                        __halves2half2(__float2half_rn(vx0), __float2half_rn(vy0));
                    *reinterpret_cast<__half2*>(&inp_out[(size_t)(row0 + 8) * DDIM + col]) =
                        __halves2half2(__float2half_rn(vx1), __float2half_rn(vy1));
                } else if (col < 2 * DDIM) {   // sigmoid(og) -> fp16
                    int c2 = col - DDIM;
                    *reinterpret_cast<__half2*>(&og_out[(size_t)row0 * DDIM + c2]) =
                        __halves2half2(__float2half_rn(fsig(vx0)), __float2half_rn(fsig(vy0)));
                    *reinterpret_cast<__half2*>(&og_out[(size_t)(row0 + 8) * DDIM + c2]) =
                        __halves2half2(__float2half_rn(fsig(vx1)), __float2half_rn(fsig(vy1)));
                } else {                       // lambda -> fp32 (precision-critical)
                    int c2 = col - 2 * DDIM;
                    float2 lv = *(const float2*)&lbp[c2];
                    float l00 = lv.x + (1.f - lv.x) * fsig(vx0);
                    float l01 = lv.y + (1.f - lv.y) * fsig(vy0);
                    float l10 = lv.x + (1.f - lv.x) * fsig(vx1);
                    float l11 = lv.y + (1.f - lv.y) * fsig(vy1);
                    *(float2*)&lam_out[(size_t)row0 * DDIM + c2]       = make_float2(l00, l01);
                    *(float2*)&lam_out[(size_t)(row0 + 8) * DDIM + c2] = make_float2(l10, l11);
                }
            } else {
                *(float2*)&C[(size_t)row0 * N + col]       = make_float2(vx0, vy0);
                *(float2*)&C[(size_t)(row0 + 8) * N + col] = make_float2(vx1, vy1);
            }
        }
    }
}

// ======================= scan (pure FMA; gates pre-activated) ===============
// seg layout: [(dir*NB+bb)*SEG + s][h]  -> h innermost, fully coalesced
__global__ __launch_bounds__(256)
void scan_pass1()
{
    int gid = blockIdx.x * blockDim.x + threadIdx.x;   // 262144
    int h   = gid & 511;
    int s   = (gid >> 9) & (SEG - 1);
    int bb  = (gid >> 15) & 3;
    int dir = gid >> 17;

    float A0 = 1.f, A1 = 1.f;
    float B0 = 0.f, B1 = 0.f, B2 = 0.f, B3 = 0.f;
    int n    = (dir == 0) ? s * LSEG : s * LSEG + LSEG - 1;
    int step = (dir == 0) ? 1 : -1;

    #pragma unroll 4
    for (int t = 0; t < LSEG; t++, n += step) {
        size_t row = (size_t)n * NBATCH + bb;
        float2 iv = __half22float2(*(const __half2*)&g_inp[row * DDIM + 2*h]);
        float2 lv = *(const float2*)&g_lam[row * DDIM + 2*h];
        float w0 = 1.f - lv.x, w1 = 1.f - lv.y;
        B0 = fmaf(lv.x, B0, w0 * iv.x);
        B1 = fmaf(lv.x, B1, w0 * iv.y);
        B2 = fmaf(lv.y, B2, w1 * iv.x);
        B3 = fmaf(lv.y, B3, w1 * iv.y);
        A0 *= lv.x;
        A1 *= lv.y;
    }
    int idx = ((dir * NBATCH + bb) * SEG + s) * HDIM + h;
    *(float2*)&g_segA[(size_t)idx * 2] = make_float2(A0, A1);
    *(float4*)&g_segB[(size_t)idx * 4] = make_float4(B0, B1, B2, B3);
}

__global__ __launch_bounds__(128)
void scan_carry()
{
    int gid = blockIdx.x * blockDim.x + threadIdx.x;
    if (gid >= 2 * NBATCH * HDIM) return;
    int h   = gid & 511;
    int bb  = (gid >> 9) & 3;
    int dir = gid >> 11;
    int base = (dir * NBATCH + bb) * SEG * HDIM + h;

    float c0 = 0.f, c1 = 0.f, c2 = 0.f, c3 = 0.f;
    if (dir == 0) {
        for (int s = 0; s < SEG; s++) {
            int idx = base + s * HDIM;
            *(float4*)&g_carry[(size_t)idx * 4] = make_float4(c0, c1, c2, c3);
            float2 a = *(const float2*)&g_segA[(size_t)idx * 2];
            float4 b = *(const float4*)&g_segB[(size_t)idx * 4];
            c0 = fmaf(a.x, c0, b.x);
            c1 = fmaf(a.x, c1, b.y);
            c2 = fmaf(a.y, c2, b.z);
            c3 = fmaf(a.y, c3, b.w);
        }
    } else {
        for (int s = SEG - 1; s >= 0; s--) {
            int idx = base + s * HDIM;
            *(float4*)&g_carry[(size_t)idx * 4] = make_float4(c0, c1, c2, c3);
            float2 a = *(const float2*)&g_segA[(size_t)idx * 2];
            float4 b = *(const float4*)&g_segB[(size_t)idx * 4];
            c0 = fmaf(a.x, c0, b.x);
            c1 = fmaf(a.x, c1, b.y);
            c2 = fmaf(a.y, c2, b.z);
            c3 = fmaf(a.y, c3, b.w);
        }
    }
}

__global__ __launch_bounds__(256)
void scan_pass3()
{
    int gid = blockIdx.x * blockDim.x + threadIdx.x;   // 262144
    int h   = gid & 511;
    int s   = (gid >> 9) & (SEG - 1);
    int bb  = (gid >> 15) & 3;
    int dir = gid >> 17;

    int idx = ((dir * NBATCH + bb) * SEG + s) * HDIM + h;
    float4 c = *(const float4*)&g_carry[(size_t)idx * 4];
    float h0 = c.x, h1 = c.y, h2 = c.z, h3 = c.w;

    float* outp = dir ? g_outr : g_outf;
    int n    = (dir == 0) ? s * LSEG : s * LSEG + LSEG - 1;
    int step = (dir == 0) ? 1 : -1;

    #pragma unroll 4
    for (int t = 0; t < LSEG; t++, n += step) {
        size_t row = (size_t)n * NBATCH + bb;
        float2 iv = __half22float2(*(const __half2*)&g_inp[row * DDIM + 2*h]);
        float2 gv = __half22float2(*(const __half2*)&g_og [row * DDIM + 2*h]);
        float2 lv = *(const float2*)&g_lam[row * DDIM + 2*h];
        float w0 = 1.f - lv.x, w1 = 1.f - lv.y;
        h0 = fmaf(lv.x, h0, w0 * iv.x);
        h1 = fmaf(lv.x, h1, w0 * iv.y);
        h2 = fmaf(lv.y, h2, w1 * iv.x);
        h3 = fmaf(lv.y, h3, w1 * iv.y);
        float o0 = gv.x * h0 + gv.y * h2;
        float o1 = gv.x * h1 + gv.y * h3;
        *(float2*)&outp[row * DDIM + h * 2] = make_float2(o0, o1);
    }
}

// layernorm over d, fused with fp16 conversion for GEMM2's A operand
__global__ __launch_bounds__(256)
void layernorm_conv_kernel(const float* __restrict__ gamma, const float* __restrict__ beta,
                           __half* __restrict__ A)
{
    int r   = blockIdx.x;
    int tid = threadIdx.x;
    __shared__ float red[256];

    float4 va = *(const float4*)&g_outf[(size_t)r * DDIM + tid * 4];
    float4 vb = *(const float4*)&g_outr[(size_t)r * DDIM + tid * 4];
    float v0 = va.x + vb.x, v1 = va.y + vb.y, v2 = va.z + vb.z, v3 = va.w + vb.w;

    red[tid] = v0 + v1 + v2 + v3;
    __syncthreads();
    #pragma unroll
    for (int off = 128; off > 0; off >>= 1) {
        if (tid < off) red[tid] += red[tid + off];
        __syncthreads();
    }
    float mu = red[0] * (1.f / DDIM);
    __syncthreads();

    float d0 = v0 - mu, d1 = v1 - mu, d2 = v2 - mu, d3 = v3 - mu;
    red[tid] = d0 * d0 + d1 * d1 + d2 * d2 + d3 * d3;
    __syncthreads();
    #pragma unroll
    for (int off = 128; off > 0; off >>= 1) {
        if (tid < off) red[tid] += red[tid + off];
        __syncthreads();
    }
    float rs = rsqrtf(red[0] * (1.f / DDIM) + 1e-5f);

    int c = tid * 4;
    float4 g4 = *(const float4*)&gamma[c];
    float4 b4 = *(const float4*)&beta[c];
    float o0 = d0 * rs * g4.x + b4.x;
    float o1 = d1 * rs * g4.y + b4.y;
    float o2 = d2 * rs * g4.z + b4.z;
    float o3 = d3 * rs * g4.w + b4.w;

    __half2 H01 = __halves2half2(__float2half_rn(o0), __float2half_rn(o1));
    __half2 H23 = __halves2half2(__float2half_rn(o2), __float2half_rn(o3));
    __half* Ap = A + (size_t)r * PK;
    *reinterpret_cast<__half2*>(Ap + c)     = H01;
    *reinterpret_cast<__half2*>(Ap + c + 2) = H23;
}

// ======================= launch =============================================
extern "C" void kernel_launch(void* const* d_in, const int* in_sizes, int n_in,
                              void* d_out, int out_size)
{
    const float* x     = (const float*)d_in[0];
    const float* lb    = (const float*)d_in[1];
    const float* W_in  = (const float*)d_in[2];
    const float* b_in  = (const float*)d_in[3];
    const float* W_out = (const float*)d_in[4];
    const float* b_out = (const float*)d_in[5];
    const float* gamma = (const float*)d_in[6];
    const float* beta  = (const float*)d_in[7];
    float* out = (float*)d_out;

    __half *p_A = nullptr, *p_B = nullptr, *p_inp = nullptr, *p_og = nullptr;
    float* p_lam = nullptr;
    cudaGetSymbolAddress((void**)&p_A,   g_Ah);
    cudaGetSymbolAddress((void**)&p_B,   g_Bh);
    cudaGetSymbolAddress((void**)&p_inp, g_inp);
    cudaGetSymbolAddress((void**)&p_og,  g_og);
    cudaGetSymbolAddress((void**)&p_lam, g_lam);

    cudaFuncSetAttribute(gemm_mma, cudaFuncAttributeMaxDynamicSharedMemorySize, SMEM_GEMM);

    // --- GEMM1 + fused gate activations (writes inp/og fp16, lambda fp32)
    convA_kernel<<<(NROWS * DDIM / 4 + 255) / 256, 256>>>(x, p_A);
    {
        dim3 g(D3 / 32, DDIM / 32);
        convB_kernel<<<g, 256>>>(W_in, p_B, D3);
    }
    {
        dim3 g(D3 / BN, NROWS / BM);   // (24, 64)
        gemm_mma<<<g, 256, SMEM_GEMM>>>(p_A, p_B, b_in, nullptr, D3, lb, 1,
                                        p_inp, p_og, p_lam);
    }

    // --- bidirectional scan (pure FMA; 262144 threads/pass)
    scan_pass1<<<262144 / 256, 256>>>();
    scan_carry<<<4096 / 128, 128>>>();
    scan_pass3<<<262144 / 256, 256>>>();

    // --- layernorm fused with A' conversion for GEMM2
    layernorm_conv_kernel<<<NROWS, 256>>>(gamma, beta, p_A);

    // --- GEMM2: out = ln @ W_out + b_out
    {
        dim3 g(DDIM / 32, DDIM / 32);
        convB_kernel<<<g, 256>>>(W_out, p_B, DDIM);
    }
    {
        dim3 g(DDIM / BN, NROWS / BM);  // (8, 64)
        gemm_mma<<<g, 256, SMEM_GEMM>>>(p_A, p_B, b_out, out, DDIM, nullptr, 0,
                                        nullptr, nullptr, nullptr);
    }
}

// round 17
// speedup vs baseline: 1.0339x; 1.0339x over previous
#include <cuda_runtime.h>
#include <cuda_fp16.h>
#include <math.h>
#include <stdint.h>

// Problem constants: n=2048, b=4, d=1024, E=2, h=512
#define NSEQ   2048
#define NBATCH 4
#define DDIM   1024
#define D3     (3*DDIM)
#define HDIM   512
#define NROWS  (NSEQ*NBATCH)   // 8192
#define SEG    64
#define LSEG   (NSEQ/SEG)      // 32

// GEMM: pure fp16 single-pass.
#define PK     1024
#define BM     128
#define BN     128
#define BKE    64
#define STAGES 3
#define NIT    16
#define ABYTES      16384
#define STAGE_BYTES 32768
#define SMEM_GEMM   (STAGES * STAGE_BYTES)   // 96 KB

#define SWZ(r, c) ((uint32_t)((r)*128 + (((c) ^ ((r)&7))*16)))

// ---------------- scratch (device globals; no cudaMalloc allowed) ----------
__device__ float g_feat[(size_t)NROWS * D3];        // 96 MB (pre-activated)
__device__ float g_segA[2*NBATCH*SEG*HDIM*2];
__device__ float g_segB[2*NBATCH*SEG*HDIM*4];
__device__ float g_carry[2*NBATCH*SEG*HDIM*4];
__device__ __half g_outf[(size_t)NROWS * DDIM];     // 16 MB fp16 (coalesced io)
__device__ __half g_outr[(size_t)NROWS * DDIM];     // 16 MB fp16
__device__ __half g_Ah[(size_t)NROWS * PK];         // 16 MB
__device__ __half g_Bh[(size_t)D3 * PK];            // 6 MB

// ======================= PTX helpers ========================================
__device__ __forceinline__ uint32_t smem_u32(const void* p) {
    uint32_t a;
    asm("{ .reg .u64 t; cvta.to.shared.u64 t, %1; cvt.u32.u64 %0, t; }" : "=r"(a) : "l"(p));
    return a;
}
__device__ __forceinline__ void cpa16(uint32_t dst, const void* src) {
    asm volatile("cp.async.cg.shared.global [%0], [%1], 16;" :: "r"(dst), "l"(src));
}
#define CP_COMMIT() asm volatile("cp.async.commit_group;" ::: "memory")
#define CP_WAIT(n)  asm volatile("cp.async.wait_group %0;" :: "n"(n) : "memory")

__device__ __forceinline__ void ldsm4(uint32_t& r0, uint32_t& r1, uint32_t& r2,
                                      uint32_t& r3, uint32_t addr) {
    asm volatile("ldmatrix.sync.aligned.m8n8.x4.shared.b16 {%0,%1,%2,%3}, [%4];"
                 : "=r"(r0), "=r"(r1), "=r"(r2), "=r"(r3) : "r"(addr));
}
__device__ __forceinline__ void mma16816(float* d, const uint32_t* a, const uint32_t* b) {
    asm volatile("mma.sync.aligned.m16n8k16.row.col.f32.f16.f16.f32 "
        "{%0,%1,%2,%3}, {%4,%5,%6,%7}, {%8,%9}, {%0,%1,%2,%3};"
        : "+f"(d[0]), "+f"(d[1]), "+f"(d[2]), "+f"(d[3])
        : "r"(a[0]), "r"(a[1]), "r"(a[2]), "r"(a[3]), "r"(b[0]), "r"(b[1]));
}

__device__ __forceinline__ float fsig(float x) { return 1.f / (1.f + __expf(-x)); }

// ======================= conversion kernels =================================
__global__ __launch_bounds__(256)
void convA_kernel(const float* __restrict__ X, __half* __restrict__ A)
{
    size_t t = (size_t)blockIdx.x * blockDim.x + threadIdx.x;
    size_t idx = t * 4;
    float4 v = *(const float4*)&X[idx];
    __half2 H01 = __halves2half2(__float2half_rn(v.x), __float2half_rn(v.y));
    __half2 H23 = __halves2half2(__float2half_rn(v.z), __float2half_rn(v.w));
    *reinterpret_cast<__half2*>(A + idx)     = H01;
    *reinterpret_cast<__half2*>(A + idx + 2) = H23;
}

__global__ __launch_bounds__(256)
void convB_kernel(const float* __restrict__ W, __half* __restrict__ Bp, int N)
{
    __shared__ float tile[32][33];
    int n0 = blockIdx.x * 32, k0 = blockIdx.y * 32;
    int tx = threadIdx.x & 31, ty = threadIdx.x >> 5;
    #pragma unroll
    for (int j = 0; j < 32; j += 8)
        tile[ty + j][tx] = W[(size_t)(k0 + ty + j) * N + n0 + tx];
    __syncthreads();
    #pragma unroll
    for (int j = 0; j < 32; j += 8) {
        int n = n0 + ty + j;
        int k = k0 + tx;
        Bp[(size_t)n * PK + k] = __float2half_rn(tile[tx][ty + j]);
    }
}

// ======================= HMMA GEMM (fp16, 1-pass) ===========================
__device__ __forceinline__ void load_stage(uint32_t sA, uint32_t sB,
    const __half* Ab, const __half* Bb, int ist, int tid)
{
    int k0 = ist * BKE;
    #pragma unroll
    for (int q = 0; q < 4; q++) {
        int g = tid + q * 256;
        int r = g >> 3, c = g & 7;
        uint32_t off = SWZ(r, c);
        cpa16(sA + off, Ab + (size_t)r * PK + k0 + c * 8);
        cpa16(sB + off, Bb + (size_t)r * PK + k0 + c * 8);
    }
}

// act: 0 = plain bias add; 1 = gates epilogue (silu / sigmoid / lambda by col)
__global__ __launch_bounds__(256, 2)
void gemm_mma(const __half* __restrict__ A, const __half* __restrict__ B,
              const float* __restrict__ bias, float* __restrict__ C, int N,
              const float* __restrict__ lbp, int act)
{
    extern __shared__ __align__(1024) char smem[];
    uint32_t sb = smem_u32(smem);

    const int tid  = threadIdx.x;
    const int wid  = tid >> 5;
    const int lane = tid & 31;
    const int m0 = blockIdx.y * BM;
    const int n0 = blockIdx.x * BN;
    const int wm = (wid >> 2) * 64;
    const int wn = (wid & 3) * 32;

    const __half* Ab = A + (size_t)m0 * PK;
    const __half* Bb = B + (size_t)n0 * PK;

    float d[4][4][4];
    #pragma unroll
    for (int i = 0; i < 4; i++)
        #pragma unroll
        for (int j = 0; j < 4; j++)
            #pragma unroll
            for (int q = 0; q < 4; q++) d[i][j][q] = 0.f;

    #pragma unroll
    for (int s = 0; s < STAGES - 1; s++) {
        load_stage(sb + s * STAGE_BYTES, sb + s * STAGE_BYTES + ABYTES, Ab, Bb, s, tid);
        CP_COMMIT();
    }

    const int a_row = wm + (lane & 15);
    const int a_ch  = (lane >> 4);
    const int b_row = wn + ((lane >> 4) * 8) + (lane & 7);
    const int b_ch  = ((lane >> 3) & 1);

    for (int it = 0; it < NIT; it++) {
        CP_WAIT(STAGES - 2);
        __syncthreads();

        if (it + STAGES - 1 < NIT) {
            int s = (it + STAGES - 1) % STAGES;
            load_stage(sb + s * STAGE_BYTES, sb + s * STAGE_BYTES + ABYTES,
                       Ab, Bb, it + STAGES - 1, tid);
        }
        CP_COMMIT();

        uint32_t sA = sb + (it % STAGES) * STAGE_BYTES;
        uint32_t sB = sA + ABYTES;

        #pragma unroll
        for (int kk = 0; kk < 4; kk++) {
            uint32_t a[4][4], b[2][4];
            #pragma unroll
            for (int mt = 0; mt < 4; mt++) {
                uint32_t addr = sA + SWZ(a_row + mt * 16, a_ch + kk * 2);
                ldsm4(a[mt][0], a[mt][1], a[mt][2], a[mt][3], addr);
            }
            #pragma unroll
            for (int nt2 = 0; nt2 < 2; nt2++) {
                uint32_t addr = sB + SWZ(b_row + nt2 * 16, b_ch + kk * 2);
                ldsm4(b[nt2][0], b[nt2][1], b[nt2][2], b[nt2][3], addr);
            }
            #pragma unroll
            for (int mt = 0; mt < 4; mt++)
                #pragma unroll
                for (int nt = 0; nt < 4; nt++)
                    mma16816(d[mt][nt], a[mt], &b[nt >> 1][(nt & 1) * 2]);
        }
    }

    const int grp = lane >> 2;
    const int tig = lane & 3;
    #pragma unroll
    for (int mt = 0; mt < 4; mt++) {
        int row0 = m0 + wm + mt * 16 + grp;
        #pragma unroll
        for (int nt = 0; nt < 4; nt++) {
            int col = n0 + wn + nt * 8 + tig * 2;
            float2 bv = *(const float2*)&bias[col];
            float vx0 = d[mt][nt][0] + bv.x, vy0 = d[mt][nt][1] + bv.y;
            float vx1 = d[mt][nt][2] + bv.x, vy1 = d[mt][nt][3] + bv.y;
            if (act) {
                if (col < DDIM) {              // silu(inp)
                    vx0 *= fsig(vx0); vy0 *= fsig(vy0);
                    vx1 *= fsig(vx1); vy1 *= fsig(vy1);
                } else if (col < 2 * DDIM) {   // sigmoid(og)
                    vx0 = fsig(vx0); vy0 = fsig(vy0);
                    vx1 = fsig(vx1); vy1 = fsig(vy1);
                } else {                       // lambda = lb + (1-lb)*sigm(fg)
                    float2 lv = *(const float2*)&lbp[col - 2 * DDIM];
                    vx0 = lv.x + (1.f - lv.x) * fsig(vx0);
                    vy0 = lv.y + (1.f - lv.y) * fsig(vy0);
                    vx1 = lv.x + (1.f - lv.x) * fsig(vx1);
                    vy1 = lv.y + (1.f - lv.y) * fsig(vy1);
                }
            }
            *(float2*)&C[(size_t)row0 * N + col]       = make_float2(vx0, vy0);
            *(float2*)&C[(size_t)(row0 + 8) * N + col] = make_float2(vx1, vy1);
        }
    }
}

// ======================= scan (pure FMA; gates pre-activated) ===============
// seg layout: [(dir*NB+bb)*SEG + s][h]  -> h innermost, fully coalesced
__global__ __launch_bounds__(256)
void scan_pass1()
{
    int gid = blockIdx.x * blockDim.x + threadIdx.x;   // 262144
    int h   = gid & 511;
    int s   = (gid >> 9) & (SEG - 1);
    int bb  = (gid >> 15) & 3;
    int dir = gid >> 17;

    float A0 = 1.f, A1 = 1.f;
    float B0 = 0.f, B1 = 0.f, B2 = 0.f, B3 = 0.f;
    int n    = (dir == 0) ? s * LSEG : s * LSEG + LSEG - 1;
    int step = (dir == 0) ? 1 : -1;

    #pragma unroll 4
    for (int t = 0; t < LSEG; t++, n += step) {
        const float* fr = g_feat + ((size_t)n * NBATCH + bb) * D3;
        float2 iv = *(const float2*)&fr[2*h];               // silu(inp)
        float2 lv = *(const float2*)&fr[2*DDIM + 2*h];      // lambda
        float w0 = 1.f - lv.x, w1 = 1.f - lv.y;
        B0 = fmaf(lv.x, B0, w0 * iv.x);
        B1 = fmaf(lv.x, B1, w0 * iv.y);
        B2 = fmaf(lv.y, B2, w1 * iv.x);
        B3 = fmaf(lv.y, B3, w1 * iv.y);
        A0 *= lv.x;
        A1 *= lv.y;
    }
    int idx = ((dir * NBATCH + bb) * SEG + s) * HDIM + h;
    *(float2*)&g_segA[(size_t)idx * 2] = make_float2(A0, A1);
    *(float4*)&g_segB[(size_t)idx * 4] = make_float4(B0, B1, B2, B3);
}

__global__ __launch_bounds__(128)
void scan_carry()
{
    int gid = blockIdx.x * blockDim.x + threadIdx.x;
    if (gid >= 2 * NBATCH * HDIM) return;
    int h   = gid & 511;
    int bb  = (gid >> 9) & 3;
    int dir = gid >> 11;
    int base = (dir * NBATCH + bb) * SEG * HDIM + h;

    float c0 = 0.f, c1 = 0.f, c2 = 0.f, c3 = 0.f;
    if (dir == 0) {
        for (int s = 0; s < SEG; s++) {
            int idx = base + s * HDIM;
            *(float4*)&g_carry[(size_t)idx * 4] = make_float4(c0, c1, c2, c3);
            float2 a = *(const float2*)&g_segA[(size_t)idx * 2];
            float4 b = *(const float4*)&g_segB[(size_t)idx * 4];
            c0 = fmaf(a.x, c0, b.x);
            c1 = fmaf(a.x, c1, b.y);
            c2 = fmaf(a.y, c2, b.z);
            c3 = fmaf(a.y, c3, b.w);
        }
    } else {
        for (int s = SEG - 1; s >= 0; s--) {
            int idx = base + s * HDIM;
            *(float4*)&g_carry[(size_t)idx * 4] = make_float4(c0, c1, c2, c3);
            float2 a = *(const float2*)&g_segA[(size_t)idx * 2];
            float4 b = *(const float4*)&g_segB[(size_t)idx * 4];
            c0 = fmaf(a.x, c0, b.x);
            c1 = fmaf(a.x, c1, b.y);
            c2 = fmaf(a.y, c2, b.z);
            c3 = fmaf(a.y, c3, b.w);
        }
    }
}

__global__ __launch_bounds__(256)
void scan_pass3()
{
    int gid = blockIdx.x * blockDim.x + threadIdx.x;   // 262144
    int h   = gid & 511;
    int s   = (gid >> 9) & (SEG - 1);
    int bb  = (gid >> 15) & 3;
    int dir = gid >> 17;

    int idx = ((dir * NBATCH + bb) * SEG + s) * HDIM + h;
    float4 c = *(const float4*)&g_carry[(size_t)idx * 4];
    float h0 = c.x, h1 = c.y, h2 = c.z, h3 = c.w;

    __half* outp = dir ? g_outr : g_outf;
    int n    = (dir == 0) ? s * LSEG : s * LSEG + LSEG - 1;
    int step = (dir == 0) ? 1 : -1;

    #pragma unroll 4
    for (int t = 0; t < LSEG; t++, n += step) {
        size_t row = (size_t)n * NBATCH + bb;
        const float* fr = g_feat + row * D3;
        float2 iv = *(const float2*)&fr[2*h];               // silu(inp)
        float2 gv = *(const float2*)&fr[DDIM   + 2*h];      // sigm(og)
        float2 lv = *(const float2*)&fr[2*DDIM + 2*h];      // lambda
        float w0 = 1.f - lv.x, w1 = 1.f - lv.y;
        h0 = fmaf(lv.x, h0, w0 * iv.x);
        h1 = fmaf(lv.x, h1, w0 * iv.y);
        h2 = fmaf(lv.y, h2, w1 * iv.x);
        h3 = fmaf(lv.y, h3, w1 * iv.y);
        float o0 = gv.x * h0 + gv.y * h2;
        float o1 = gv.x * h1 + gv.y * h3;
        // coalesced half2 store (4B x 32 lanes = 128B contiguous per warp)
        *reinterpret_cast<__half2*>(&outp[row * DDIM + h * 2]) =
            __halves2half2(__float2half_rn(o0), __float2half_rn(o1));
    }
}

// layernorm over d, fused with fp16 conversion for GEMM2's A operand
__global__ __launch_bounds__(256)
void layernorm_conv_kernel(const float* __restrict__ gamma, const float* __restrict__ beta,
                           __half* __restrict__ A)
{
    int r   = blockIdx.x;
    int tid = threadIdx.x;
    __shared__ float red[256];

    // 4 channels per thread: two half2 loads from each of outf/outr
    const __half2* pf = reinterpret_cast<const __half2*>(&g_outf[(size_t)r * DDIM + tid * 4]);
    const __half2* pr = reinterpret_cast<const __half2*>(&g_outr[(size_t)r * DDIM + tid * 4]);
    float2 f01 = __half22float2(pf[0]);
    float2 f23 = __half22float2(pf[1]);
    float2 r01 = __half22float2(pr[0]);
    float2 r23 = __half22float2(pr[1]);
    float v0 = f01.x + r01.x, v1 = f01.y + r01.y;
    float v2 = f23.x + r23.x, v3 = f23.y + r23.y;

    red[tid] = v0 + v1 + v2 + v3;
    __syncthreads();
    #pragma unroll
    for (int off = 128; off > 0; off >>= 1) {
        if (tid < off) red[tid] += red[tid + off];
        __syncthreads();
    }
    float mu = red[0] * (1.f / DDIM);
    __syncthreads();

    float d0 = v0 - mu, d1 = v1 - mu, d2 = v2 - mu, d3 = v3 - mu;
    red[tid] = d0 * d0 + d1 * d1 + d2 * d2 + d3 * d3;
    __syncthreads();
    #pragma unroll
    for (int off = 128; off > 0; off >>= 1) {
        if (tid < off) red[tid] += red[tid + off];
        __syncthreads();
    }
    float rs = rsqrtf(red[0] * (1.f / DDIM) + 1e-5f);

    int c = tid * 4;
    float4 g4 = *(const float4*)&gamma[c];
    float4 b4 = *(const float4*)&beta[c];
    float o0 = d0 * rs * g4.x + b4.x;
    float o1 = d1 * rs * g4.y + b4.y;
    float o2 = d2 * rs * g4.z + b4.z;
    float o3 = d3 * rs * g4.w + b4.w;

    __half2 H01 = __halves2half2(__float2half_rn(o0), __float2half_rn(o1));
    __half2 H23 = __halves2half2(__float2half_rn(o2), __float2half_rn(o3));
    __half* Ap = A + (size_t)r * PK;
    *reinterpret_cast<__half2*>(Ap + c)     = H01;
    *reinterpret_cast<__half2*>(Ap + c + 2) = H23;
}

// ======================= launch =============================================
extern "C" void kernel_launch(void* const* d_in, const int* in_sizes, int n_in,
                              void* d_out, int out_size)
{
    const float* x     = (const float*)d_in[0];
    const float* lb    = (const float*)d_in[1];
    const float* W_in  = (const float*)d_in[2];
    const float* b_in  = (const float*)d_in[3];
    const float* W_out = (const float*)d_in[4];
    const float* b_out = (const float*)d_in[5];
    const float* gamma = (const float*)d_in[6];
    const float* beta  = (const float*)d_in[7];
    float* out = (float*)d_out;

    float* p_feat = nullptr;
    __half *p_A = nullptr, *p_B = nullptr;
    cudaGetSymbolAddress((void**)&p_feat, g_feat);
    cudaGetSymbolAddress((void**)&p_A,    g_Ah);
    cudaGetSymbolAddress((void**)&p_B,    g_Bh);

    cudaFuncSetAttribute(gemm_mma, cudaFuncAttributeMaxDynamicSharedMemorySize, SMEM_GEMM);

    // --- GEMM1 + fused gate activations: feat = act(x @ W_in + b_in)
    convA_kernel<<<(NROWS * DDIM / 4 + 255) / 256, 256>>>(x, p_A);
    {
        dim3 g(D3 / 32, DDIM / 32);
        convB_kernel<<<g, 256>>>(W_in, p_B, D3);
    }
    {
        dim3 g(D3 / BN, NROWS / BM);   // (24, 64)
        gemm_mma<<<g, 256, SMEM_GEMM>>>(p_A, p_B, b_in, p_feat, D3, lb, 1);
    }

    // --- bidirectional scan (pure FMA; 262144 threads/pass)
    scan_pass1<<<262144 / 256, 256>>>();
    scan_carry<<<4096 / 128, 128>>>();
    scan_pass3<<<262144 / 256, 256>>>();

    // --- layernorm fused with A' conversion for GEMM2
    layernorm_conv_kernel<<<NROWS, 256>>>(gamma, beta, p_A);

    // --- GEMM2: out = ln @ W_out + b_out
    {
        dim3 g(DDIM / 32, DDIM / 32);
        convB_kernel<<<g, 256>>>(W_out, p_B, DDIM);
    }
    {
        dim3 g(DDIM / BN, NROWS / BM);  // (8, 64)
        gemm_mma<<<g, 256, SMEM_GEMM>>>(p_A, p_B, b_out, out, DDIM, nullptr, 0);
    }
}